// round 14
// baseline (speedup 1.0000x reference)
#include <cuda_runtime.h>
#include <cuda_bf16.h>
#include <cuda_fp16.h>
#include <cstdint>
#include <cstddef>

#define NTOK 4096
#define NCH  512
#define NB1C 2097152u   // NTOK*NCH

typedef __nv_bfloat16 bf16;

// 256 MB static scratch (bss) — no runtime allocation.
__device__ float g_scratch[64u * 1024u * 1024u];

// ---------------------------------------------------------------------------
// PTX helpers (base ISA: cp.async, ldmatrix, mma.sync bf16 + e4m3)
// ---------------------------------------------------------------------------
__device__ __forceinline__ uint32_t s2u(const void* p) {
    uint32_t r;
    asm("{ .reg .u64 t; cvta.to.shared.u64 t, %1; cvt.u32.u64 %0, t; }"
        : "=r"(r) : "l"(p));
    return r;
}
#define CP_ASYNC16(s, g)                                                       \
    asm volatile("cp.async.cg.shared.global [%0], [%1], 16;" ::                \
                 "r"(s), "l"(g))
#define CP_COMMIT() asm volatile("cp.async.commit_group;" ::: "memory")
#define CP_WAIT(n)  asm volatile("cp.async.wait_group %0;" :: "n"(n) : "memory")

__device__ __forceinline__ void ldm_x4(uint32_t& r0, uint32_t& r1,
                                       uint32_t& r2, uint32_t& r3,
                                       uint32_t addr) {
    asm volatile("ldmatrix.sync.aligned.m8n8.x4.shared.b16 {%0,%1,%2,%3}, [%4];"
                 : "=r"(r0), "=r"(r1), "=r"(r2), "=r"(r3) : "r"(addr));
}
__device__ __forceinline__ void mma16816(float* c, const uint32_t* a,
                                         uint32_t b0, uint32_t b1) {
    asm volatile(
        "mma.sync.aligned.m16n8k16.row.col.f32.bf16.bf16.f32 "
        "{%0,%1,%2,%3}, {%4,%5,%6,%7}, {%8,%9}, {%0,%1,%2,%3};"
        : "+f"(c[0]), "+f"(c[1]), "+f"(c[2]), "+f"(c[3])
        : "r"(a[0]), "r"(a[1]), "r"(a[2]), "r"(a[3]), "r"(b0), "r"(b1));
}
// fp8 e4m3 MMA with f16 accumulators (2 regs, packed half2 per 8-row group)
__device__ __forceinline__ void mma16832h(uint32_t* c, const uint32_t* a,
                                          uint32_t b0, uint32_t b1) {
    asm volatile(
        "mma.sync.aligned.m16n8k32.row.col.f16.e4m3.e4m3.f16 "
        "{%0,%1}, {%2,%3,%4,%5}, {%6,%7}, {%0,%1};"
        : "+r"(c[0]), "+r"(c[1])
        : "r"(a[0]), "r"(a[1]), "r"(a[2]), "r"(a[3]), "r"(b0), "r"(b1));
}
// pack two fp32 -> e4m3x2 (lo in low byte)
__device__ __forceinline__ uint16_t pack_e4m3(float lo, float hi) {
    uint16_t r;
    asm("cvt.rn.satfinite.e4m3x2.f32 %0, %1, %2;" : "=h"(r) : "f"(hi), "f"(lo));
    return r;
}

// ---------------------------------------------------------------------------
// prep kernel: GroupNorm (blocks 0-63) + weight cvt (blocks 64-1087) +
// bias concat / rsum zero (block 1088) + O zero (blocks 1089-1216).
// ---------------------------------------------------------------------------
__global__ __launch_bounds__(256) void prep_kernel(
    const float* __restrict__ x, const float* __restrict__ gs,
    const float* __restrict__ gb, bf16* __restrict__ t,
    const float* __restrict__ wq, const float* __restrict__ wk,
    const float* __restrict__ wv, const float* __restrict__ wp,
    bf16* __restrict__ o01, bf16* __restrict__ o2, bf16* __restrict__ o3,
    const float* __restrict__ bq, const float* __restrict__ bk,
    float* __restrict__ bqk, float* __restrict__ rsum,
    bf16* __restrict__ Ozero) {
    int blk = blockIdx.x;
    int tid = threadIdx.x;

    if (blk >= 1089) {           // zero O (split-K accumulation target)
        int lb = blk - 1089;     // 128 blocks x 64KB = 8MB
        uint4* o4 = (uint4*)Ozero + (size_t)lb * 4096;
#pragma unroll
        for (int i = 0; i < 16; i++)
            o4[tid + i * 256] = make_uint4(0u, 0u, 0u, 0u);
        return;
    }
    if (blk == 1088) {           // bias concat + rsum zero
        bqk[tid]       = bq[tid];
        bqk[tid + 256] = bq[tid + 256];
        bqk[tid + 512] = bk[tid];
        bqk[tid + 768] = bk[tid + 256];
        float4* r4 = (float4*)rsum;
#pragma unroll
        for (int i = 0; i < 8; i++)
            r4[tid + i * 256] = make_float4(0.f, 0.f, 0.f, 0.f);
        return;
    }
    if (blk >= 64) {             // weight fp32 -> bf16
        int lb = blk - 64;
        int which = lb >> 8;
        const float* in = (which == 0) ? wq : (which == 1) ? wk :
                          (which == 2) ? wv : wp;
        bf16* out = (which == 0) ? o01 : (which == 1) ? (o01 + 512 * 512) :
                    (which == 2) ? o2 : o3;
        int i = (lb & 255) * 256 + tid;
        float4 v = ((const float4*)in)[i];
        __nv_bfloat162 a = __floats2bfloat162_rn(v.x, v.y);
        __nv_bfloat162 b = __floats2bfloat162_rn(v.z, v.w);
        ((__nv_bfloat162*)out)[2 * i]     = a;
        ((__nv_bfloat162*)out)[2 * i + 1] = b;
        return;
    }

    // ---- GroupNorm: one block per (batch, group) ----
    int b = blk >> 5;
    int g = blk & 31;
    const float* base = x + ((size_t)(b * NCH + g * 16)) * NTOK;

    float s = 0.f, ss = 0.f;
    const float4* b4 = (const float4*)base;
    for (int i = tid; i < 16 * NTOK / 4; i += 256) {
        float4 v = b4[i];
        s  += v.x + v.y + v.z + v.w;
        ss += v.x * v.x + v.y * v.y + v.z * v.z + v.w * v.w;
    }
    __shared__ float rs[256], rss[256];
    rs[tid] = s; rss[tid] = ss;
    __syncthreads();
    for (int st = 128; st > 0; st >>= 1) {
        if (tid < st) { rs[tid] += rs[tid + st]; rss[tid] += rss[tid + st]; }
        __syncthreads();
    }
    float mean = rs[0] * (1.f / 65536.f);
    float var  = rss[0] * (1.f / 65536.f) - mean * mean;
    float inv  = rsqrtf(var + 1e-6f);

    __shared__ float Acf[16], Bcf[16];
    if (tid < 16) {
        float scv = gs[g * 16 + tid], biv = gb[g * 16 + tid];
        Acf[tid] = scv * inv;
        Bcf[tid] = biv - mean * scv * inv;
    }
    __shared__ float tile[16][257];
    __syncthreads();

    for (int tb = 0; tb < 16; tb++) {
        int p0 = tb * 256;
        for (int idx = tid; idx < 4096; idx += 256) {
            int cc = idx >> 8, pp = idx & 255;
            tile[cc][pp] = base[cc * NTOK + p0 + pp] * Acf[cc] + Bcf[cc];
        }
        __syncthreads();
        for (int idx = tid; idx < 4096; idx += 256) {
            int pp = idx >> 4, cc = idx & 15;
            t[((size_t)(b * NTOK + p0 + pp)) * NCH + g * 16 + cc] =
                __float2bfloat16(tile[cc][pp]);
        }
        __syncthreads();
    }
}

// ===========================================================================
// bf16 mma.sync GEMM body: C = alpha * A[M,K].B[N,K]^T (+biases/residual).
// Outputs: Cf(fp32) | Cb(bf16) | C8(e4m3, ldC/sC in bytes).
// CTA 128x128, BK=64, 8 warps, 3-stage cp.async, swizzled 128B rows.
// ===========================================================================
#define STG 32768
#define GEMM_SMEM (3 * STG)
__device__ __forceinline__ void gemm_bf16_body(
    int bxi, int byi, int bzi,
    const bf16* __restrict__ A, const bf16* __restrict__ B,
    int K, int lda, int ldb, int ldC,
    size_t sA, size_t sB, size_t sC,
    float alpha,
    const float* __restrict__ brow, const float* __restrict__ bcol,
    const float* __restrict__ res, size_t sRes,
    float* __restrict__ Cf, bf16* __restrict__ Cb, uint8_t* __restrict__ C8,
    char* smem) {
    const int tid = threadIdx.x;
    const int wid = tid >> 5, lane = tid & 31;
    const int wm = wid & 1, wn = wid >> 1;
    const int bm = byi * 128, bn = bxi * 128;
    A += (size_t)bzi * sA;
    B += (size_t)bzi * sB;
    const size_t coff = (size_t)bzi * sC;
    if (res) res += (size_t)bzi * sRes;

    const int NC = K >> 6;

    const int lr  = tid >> 2;
    const int lcb = (tid & 3) * 16;
    const uint32_t lsc = (uint32_t)((lr & 7) << 4);
    const uint32_t c0s = (uint32_t)lcb ^ lsc;
    const uint32_t c1s = c0s ^ 64u;
    const uint32_t ro0 = (uint32_t)(lr * 128);
    const uint32_t ro1 = ro0 + 64 * 128;
    const size_t lda2 = (size_t)lda * 2, ldb2 = (size_t)ldb * 2;
    const char* aR0 = (const char*)(A + (size_t)(bm + lr) * lda) + lcb;
    const char* aR1 = aR0 + 64 * lda2;
    const char* bR0 = (const char*)(B + (size_t)(bn + lr) * ldb) + lcb;
    const char* bR1 = bR0 + 64 * ldb2;

    float acc[4][4][4];
#pragma unroll
    for (int mi = 0; mi < 4; mi++)
#pragma unroll
        for (int ni = 0; ni < 4; ni++)
#pragma unroll
            for (int q = 0; q < 4; q++) acc[mi][ni][q] = 0.f;

    const uint32_t msc = (uint32_t)((lane & 7) << 4);
    const uint32_t h16 = (uint32_t)((lane >> 4) << 4);
    uint32_t kc[4];
#pragma unroll
    for (int ks = 0; ks < 4; ks++) kc[ks] = ((uint32_t)(ks * 32) + h16) ^ msc;
    uint32_t arow[4], brow_off[2];
#pragma unroll
    for (int mi = 0; mi < 4; mi++)
        arow[mi] = (uint32_t)((wm * 64 + mi * 16 + (lane & 15)) * 128);
#pragma unroll
    for (int nb = 0; nb < 2; nb++)
        brow_off[nb] = (uint32_t)(16384 + (wn * 32 + nb * 16 + (lane & 15)) * 128);

    const uint32_t sbase = s2u(smem);

#define ISSUE(st_, i_)                                                         \
    do {                                                                       \
        uint32_t sa = sbase + (uint32_t)(st_) * STG;                           \
        size_t kb = (size_t)(i_) * 128;                                        \
        CP_ASYNC16(sa + ro0 + c0s,          aR0 + kb);                         \
        CP_ASYNC16(sa + ro0 + c1s,          aR0 + kb + 64);                    \
        CP_ASYNC16(sa + ro1 + c0s,          aR1 + kb);                         \
        CP_ASYNC16(sa + ro1 + c1s,          aR1 + kb + 64);                    \
        CP_ASYNC16(sa + 16384 + ro0 + c0s,  bR0 + kb);                         \
        CP_ASYNC16(sa + 16384 + ro0 + c1s,  bR0 + kb + 64);                    \
        CP_ASYNC16(sa + 16384 + ro1 + c0s,  bR1 + kb);                         \
        CP_ASYNC16(sa + 16384 + ro1 + c1s,  bR1 + kb + 64);                    \
    } while (0)
#define LOAD_FRAGS(ks_)                                                        \
    do {                                                                       \
        _Pragma("unroll")                                                      \
        for (int mi = 0; mi < 4; mi++)                                         \
            ldm_x4(areg[mi][0], areg[mi][1], areg[mi][2], areg[mi][3],         \
                   base + arow[mi] + kc[ks_]);                                 \
        _Pragma("unroll")                                                      \
        for (int nb = 0; nb < 2; nb++)                                         \
            ldm_x4(breg[nb][0], breg[nb][1], breg[nb][2], breg[nb][3],         \
                   base + brow_off[nb] + kc[ks_]);                             \
    } while (0)
#define DO_MMAS()                                                              \
    do {                                                                       \
        _Pragma("unroll")                                                      \
        for (int mi = 0; mi < 4; mi++)                                         \
            _Pragma("unroll")                                                  \
            for (int ni = 0; ni < 4; ni++) {                                   \
                uint32_t b0 = breg[ni >> 1][ni & 1];                           \
                uint32_t b1 = breg[ni >> 1][(ni & 1) + 2];                     \
                mma16816(acc[mi][ni], areg[mi], b0, b1);                       \
            }                                                                  \
    } while (0)

    ISSUE(0, 0); CP_COMMIT();
    ISSUE(1, 1); CP_COMMIT();

    int st = 0;
    for (int i = 0; i < NC; i++) {
        if (i + 1 < NC) { CP_WAIT(1); } else { CP_WAIT(0); }
        __syncthreads();
        uint32_t base = sbase + (uint32_t)st * STG;
        uint32_t areg[4][4], breg[2][4];
        LOAD_FRAGS(0);
        if (i + 2 < NC) {
            int w2 = st + 2; if (w2 >= 3) w2 -= 3;
            ISSUE(w2, i + 2); CP_COMMIT();
        }
        DO_MMAS();
#pragma unroll
        for (int ks = 1; ks < 4; ks++) { LOAD_FRAGS(ks); DO_MMAS(); }
        st++; if (st >= 3) st = 0;
    }
#undef ISSUE
#undef LOAD_FRAGS
#undef DO_MMAS

    float bc[8];
#pragma unroll
    for (int ni = 0; ni < 4; ni++) {
        int col = bn + wn * 32 + ni * 8 + (lane & 3) * 2;
        bc[2 * ni]     = bcol ? bcol[col]     : 0.f;
        bc[2 * ni + 1] = bcol ? bcol[col + 1] : 0.f;
    }
#pragma unroll
    for (int mi = 0; mi < 4; mi++) {
#pragma unroll
        for (int h = 0; h < 2; h++) {
            int row = bm + wm * 64 + mi * 16 + (lane >> 2) + 8 * h;
            float rb = brow ? brow[row] : 0.f;
            size_t rowbase = coff + (size_t)row * ldC;
#pragma unroll
            for (int ni = 0; ni < 4; ni++) {
                int col = bn + wn * 32 + ni * 8 + (lane & 3) * 2;
                float v0 = acc[mi][ni][2 * h]     * alpha + rb + bc[2 * ni];
                float v1 = acc[mi][ni][2 * h + 1] * alpha + rb + bc[2 * ni + 1];
                if (res) {
                    v0 += res[(size_t)row * ldC + col];
                    v1 += res[(size_t)row * ldC + col + 1];
                }
                if (C8) {
                    *(uint16_t*)(C8 + rowbase + col) = pack_e4m3(v0, v1);
                } else if (Cb) {
                    __nv_bfloat162 hv = __floats2bfloat162_rn(v0, v1);
                    *(__nv_bfloat162*)(Cb + rowbase + col) = hv;
                } else {
                    *(float2*)(Cf + rowbase + col) = make_float2(v0, v1);
                }
            }
        }
    }
}

__global__ __launch_bounds__(256, 2) void gemm_bf16(
    const bf16* __restrict__ A, const bf16* __restrict__ B,
    int K, int lda, int ldb, int ldC,
    size_t sA, size_t sB, size_t sC,
    float alpha,
    const float* __restrict__ brow, const float* __restrict__ bcol,
    const float* __restrict__ res, size_t sRes,
    float* __restrict__ Cf, bf16* __restrict__ Cb, uint8_t* __restrict__ C8) {
    extern __shared__ __align__(16) char smem[];
    gemm_bf16_body(blockIdx.x, blockIdx.y, blockIdx.z, A, B, K, lda, ldb, ldC,
                   sA, sB, sC, alpha, brow, bcol, res, sRes, Cf, Cb, C8, smem);
}

// Fused QK + V launch: flat grid of 768 CTAs.
__global__ __launch_bounds__(256, 2) void gemm_qkv(
    const bf16* __restrict__ T, const bf16* __restrict__ Wqk,
    const bf16* __restrict__ Wv,
    const float* __restrict__ bqk, const float* __restrict__ bv,
    uint8_t* __restrict__ QK8, uint8_t* __restrict__ V8) {
    extern __shared__ __align__(16) char smem[];
    int id = blockIdx.x;
    if (id < 512) {
        int z = id >> 8, rem = id & 255;
        gemm_bf16_body(rem & 7, rem >> 3, z, T, Wqk, NCH, NCH, NCH, 1024,
                       NB1C, 0, 2 * (size_t)NB1C, 1.f, nullptr, bqk,
                       nullptr, 0, nullptr, nullptr, QK8, smem);
    } else {
        int id2 = id - 512;
        int z = id2 >> 7, rem = id2 & 127;
        gemm_bf16_body(rem & 31, rem >> 5, z, Wv, T, NCH, NCH, NCH, NTOK,
                       0, NB1C, NB1C, 1.f, bv, nullptr,
                       nullptr, 0, nullptr, nullptr, V8, smem);
    }
}

// ===========================================================================
// e4m3 mma.sync GEMM with f16 accumulators. 128B smem row = K=128 fp8.
// Modes:  C8exp != 0 : write exp(acc*alpha) as e4m3, atomicAdd row sums.
//         else       : Cb = acc * alpha / rsum_div[row]; if split2, K is half
//                      of the full reduction and z = split*2+batch, partials
//                      are combined via atomicAdd bf16x2 (O pre-zeroed).
// lda/ldb/sA/sB and (for C8exp) ldC/sC are in BYTES.
// ===========================================================================
__global__ __launch_bounds__(256, 2) void gemm_fp8(
    const uint8_t* __restrict__ A, const uint8_t* __restrict__ B,
    int K, int lda, int ldb, int ldC,
    size_t sA, size_t sB, size_t sC,
    float alpha,
    uint8_t* __restrict__ C8exp, float* __restrict__ rsum_out,
    bf16* __restrict__ Cb, const float* __restrict__ rsum_div,
    int split2) {
    extern __shared__ __align__(16) char smem[];

    const int tid = threadIdx.x;
    const int wid = tid >> 5, lane = tid & 31;
    const int wm = wid & 1, wn = wid >> 1;
    const int bm = blockIdx.y * 128, bn = blockIdx.x * 128;

    int zb = blockIdx.z;
    size_t kofs = 0;
    if (split2) { kofs = (size_t)(zb >> 1) * (size_t)K; zb &= 1; }
    A += (size_t)zb * sA;
    B += (size_t)zb * sB;
    const size_t coff = (size_t)zb * sC;

    const int NC = K >> 7;                       // K=128 per stage

    const int lr  = tid >> 2;
    const int lcb = (tid & 3) * 16;
    const uint32_t lsc = (uint32_t)((lr & 7) << 4);
    const uint32_t c0s = (uint32_t)lcb ^ lsc;
    const uint32_t c1s = c0s ^ 64u;
    const uint32_t ro0 = (uint32_t)(lr * 128);
    const uint32_t ro1 = ro0 + 64 * 128;
    const char* aR0 = (const char*)A + (size_t)(bm + lr) * lda + kofs + lcb;
    const char* aR1 = aR0 + (size_t)64 * lda;
    const char* bR0 = (const char*)B + (size_t)(bn + lr) * ldb + kofs + lcb;
    const char* bR1 = bR0 + (size_t)64 * ldb;

    uint32_t acc[4][4][2];
#pragma unroll
    for (int mi = 0; mi < 4; mi++)
#pragma unroll
        for (int ni = 0; ni < 4; ni++) {
            acc[mi][ni][0] = 0u;
            acc[mi][ni][1] = 0u;
        }

    const uint32_t msc = (uint32_t)((lane & 7) << 4);
    const uint32_t h16 = (uint32_t)((lane >> 4) << 4);
    uint32_t kc[4];
#pragma unroll
    for (int ks = 0; ks < 4; ks++) kc[ks] = ((uint32_t)(ks * 32) + h16) ^ msc;
    uint32_t arow[4], brow_off[2];
#pragma unroll
    for (int mi = 0; mi < 4; mi++)
        arow[mi] = (uint32_t)((wm * 64 + mi * 16 + (lane & 15)) * 128);
#pragma unroll
    for (int nb = 0; nb < 2; nb++)
        brow_off[nb] = (uint32_t)(16384 + (wn * 32 + nb * 16 + (lane & 15)) * 128);

    const uint32_t sbase = s2u(smem);

#define ISSUE(st_, i_)                                                         \
    do {                                                                       \
        uint32_t sa = sbase + (uint32_t)(st_) * STG;                           \
        size_t kb = (size_t)(i_) * 128;                                        \
        CP_ASYNC16(sa + ro0 + c0s,          aR0 + kb);                         \
        CP_ASYNC16(sa + ro0 + c1s,          aR0 + kb + 64);                    \
        CP_ASYNC16(sa + ro1 + c0s,          aR1 + kb);                         \
        CP_ASYNC16(sa + ro1 + c1s,          aR1 + kb + 64);                    \
        CP_ASYNC16(sa + 16384 + ro0 + c0s,  bR0 + kb);                         \
        CP_ASYNC16(sa + 16384 + ro0 + c1s,  bR0 + kb + 64);                    \
        CP_ASYNC16(sa + 16384 + ro1 + c0s,  bR1 + kb);                         \
        CP_ASYNC16(sa + 16384 + ro1 + c1s,  bR1 + kb + 64);                    \
    } while (0)
#define LOAD_FRAGS(ks_)                                                        \
    do {                                                                       \
        _Pragma("unroll")                                                      \
        for (int mi = 0; mi < 4; mi++)                                         \
            ldm_x4(areg[mi][0], areg[mi][1], areg[mi][2], areg[mi][3],         \
                   base + arow[mi] + kc[ks_]);                                 \
        _Pragma("unroll")                                                      \
        for (int nb = 0; nb < 2; nb++)                                         \
            ldm_x4(breg[nb][0], breg[nb][1], breg[nb][2], breg[nb][3],         \
                   base + brow_off[nb] + kc[ks_]);                             \
    } while (0)
#define DO_MMAS()                                                              \
    do {                                                                       \
        _Pragma("unroll")                                                      \
        for (int mi = 0; mi < 4; mi++)                                         \
            _Pragma("unroll")                                                  \
            for (int ni = 0; ni < 4; ni++) {                                   \
                uint32_t b0 = breg[ni >> 1][ni & 1];                           \
                uint32_t b1 = breg[ni >> 1][(ni & 1) + 2];                     \
                mma16832h(acc[mi][ni], areg[mi], b0, b1);                      \
            }                                                                  \
    } while (0)

    ISSUE(0, 0); CP_COMMIT();
    ISSUE(1, 1); CP_COMMIT();

    int st = 0;
    for (int i = 0; i < NC; i++) {
        if (i + 1 < NC) { CP_WAIT(1); } else { CP_WAIT(0); }
        __syncthreads();
        uint32_t base = sbase + (uint32_t)st * STG;
        uint32_t areg[4][4], breg[2][4];
        LOAD_FRAGS(0);
        if (i + 2 < NC) {
            int w2 = st + 2; if (w2 >= 3) w2 -= 3;
            ISSUE(w2, i + 2); CP_COMMIT();
        }
        DO_MMAS();
#pragma unroll
        for (int ks = 1; ks < 4; ks++) { LOAD_FRAGS(ks); DO_MMAS(); }
        st++; if (st >= 3) st = 0;
    }
#undef ISSUE
#undef LOAD_FRAGS
#undef DO_MMAS

    const int rows_total = gridDim.y * 128;

    if (C8exp) {
        float* rs_base = rsum_out + (size_t)zb * rows_total;
#pragma unroll
        for (int mi = 0; mi < 4; mi++) {
#pragma unroll
            for (int h = 0; h < 2; h++) {
                int row = bm + wm * 64 + mi * 16 + (lane >> 2) + 8 * h;
                size_t rowbase = coff + (size_t)row * ldC;
                float rsum = 0.f;
#pragma unroll
                for (int ni = 0; ni < 4; ni++) {
                    int col = bn + wn * 32 + ni * 8 + (lane & 3) * 2;
                    float2 f = __half22float2(
                        *(const __half2*)&acc[mi][ni][h]);
                    float e0 = __expf(f.x * alpha);
                    float e1 = __expf(f.y * alpha);
                    rsum += e0 + e1;
                    *(uint16_t*)(C8exp + rowbase + col) = pack_e4m3(e0, e1);
                }
                rsum += __shfl_xor_sync(0xFFFFFFFFu, rsum, 1);
                rsum += __shfl_xor_sync(0xFFFFFFFFu, rsum, 2);
                if ((lane & 3) == 0) atomicAdd(rs_base + row, rsum);
            }
        }
        return;
    }

    const float* rd_base = rsum_div + (size_t)zb * rows_total;
#pragma unroll
    for (int mi = 0; mi < 4; mi++) {
#pragma unroll
        for (int h = 0; h < 2; h++) {
            int row = bm + wm * 64 + mi * 16 + (lane >> 2) + 8 * h;
            float rscale = alpha / rd_base[row];
            size_t rowbase = coff + (size_t)row * ldC;
#pragma unroll
            for (int ni = 0; ni < 4; ni++) {
                int col = bn + wn * 32 + ni * 8 + (lane & 3) * 2;
                float2 f = __half22float2(*(const __half2*)&acc[mi][ni][h]);
                __nv_bfloat162 hv =
                    __floats2bfloat162_rn(f.x * rscale, f.y * rscale);
                if (split2) {
                    atomicAdd((__nv_bfloat162*)(Cb + rowbase + col), hv);
                } else {
                    *(__nv_bfloat162*)(Cb + rowbase + col) = hv;
                }
            }
        }
    }
}

// ---------------------------------------------------------------------------
// Orchestration: 5 launches.
// ---------------------------------------------------------------------------
extern "C" void kernel_launch(void* const* d_in, const int* in_sizes, int n_in,
                              void* d_out, int out_size) {
    const float* x  = (const float*)d_in[0];
    const float* gs = (const float*)d_in[1];
    const float* gb = (const float*)d_in[2];
    const float* wq = (const float*)d_in[3];
    const float* bq = (const float*)d_in[4];
    const float* wk = (const float*)d_in[5];
    const float* bk = (const float*)d_in[6];
    const float* wv = (const float*)d_in[7];
    const float* bv = (const float*)d_in[8];
    const float* wp = (const float*)d_in[9];
    const float* bp = (const float*)d_in[10];
    float* y = (float*)d_out;

    float* scratch = nullptr;
    cudaGetSymbolAddress((void**)&scratch, g_scratch);
    char* cb = (char*)scratch;

    const size_t NB1 = (size_t)NTOK * NCH;     // 2097152
    const size_t SB1 = (size_t)NTOK * NTOK;    // 16777216
    const size_t TB  = 2 * NB1 * 2;            // 8 MB (bf16 T, 2 batches)
    const size_t WB  = (size_t)NCH * NCH * 2;  // 512 KB per bf16 weight

    bf16*    T    = (bf16*)cb;                                // 8 MB
    bf16*    Wqk  = (bf16*)(cb + TB);                         // 1 MB
    bf16*    Wv   = (bf16*)(cb + TB + 2 * WB);
    bf16*    Wp   = (bf16*)(cb + TB + 3 * WB);
    float*   bqk  = (float*)(cb + TB + 4 * WB);               // 4 KB
    uint8_t* QK8  = (uint8_t*)(cb + TB + 4 * WB + 8192);      // 8 MB (fp8)
    uint8_t* V8   = QK8 + 2 * NB1 * 2;                        // 4 MB (fp8)
    uint8_t* P8   = V8 + 2 * NB1;                             // 32 MB (fp8)
    bf16*    O    = (bf16*)(P8 + 2 * SB1);                    // 8 MB
    float*   rsum = (float*)((char*)O + TB);                  // 32 KB

    cudaFuncSetAttribute(gemm_bf16, cudaFuncAttributeMaxDynamicSharedMemorySize,
                         GEMM_SMEM);
    cudaFuncSetAttribute(gemm_qkv, cudaFuncAttributeMaxDynamicSharedMemorySize,
                         GEMM_SMEM);
    cudaFuncSetAttribute(gemm_fp8, cudaFuncAttributeMaxDynamicSharedMemorySize,
                         GEMM_SMEM);

    // GN + weight cvt + bias concat + rsum zero + O zero, one launch
    prep_kernel<<<1217, 256>>>(x, gs, gb, T, wq, wk, wv, wp,
                               Wqk, Wv, Wp, bq, bk, bqk, rsum, O);

    // QK8 = e4m3(T.Wqk^T + bqk)  and  V8 = e4m3(Wv.T^T + bv), one launch
    gemm_qkv<<<768, 256, GEMM_SMEM>>>(T, Wqk, Wv, bqk, bv, QK8, V8);

    // P8[b,n,n] = e4m3( exp((Q8 . K8^T) * c^-0.5) ), rowsum accumulated
    gemm_fp8<<<dim3(32, 32, 2), 256, GEMM_SMEM>>>(
        QK8, QK8 + 512, NCH, 1024, 1024, NTOK, 2 * NB1, 2 * NB1, SB1,
        0.044194173824159216f, P8, rsum, nullptr, nullptr, 0);
    // O[b,n,c] += bf16( (P8 . V8^T) / rowsum ), split-K=2 (512 CTAs)
    gemm_fp8<<<dim3(4, 32, 4), 256, GEMM_SMEM>>>(
        P8, V8, NTOK / 2, NTOK, NTOK, NCH, SB1, NB1, NB1, 1.f,
        nullptr, nullptr, O, rsum, 1);
    // Y[b,c,n] = Wp . O^T + bp + x (row bias + residual) -> fp32
    gemm_bf16<<<dim3(32, 4, 2), 256, GEMM_SMEM>>>(
        Wp, O, NCH, NCH, NCH, NTOK, 0, NB1, NB1, 1.f,
        bp, nullptr, x, NB1, y, nullptr, nullptr);
}

// round 16
// speedup vs baseline: 1.0613x; 1.0613x over previous
#include <cuda_runtime.h>
#include <cuda_bf16.h>
#include <cuda_fp16.h>
#include <cstdint>
#include <cstddef>

#define NTOK 4096
#define NCH  512
#define NB1C 2097152u   // NTOK*NCH (elements; also bytes for fp8 buffers)
#define SB1C 16777216u  // NTOK*NTOK

typedef __nv_bfloat16 bf16;

// 256 MB static scratch (bss) — no runtime allocation.
__device__ float g_scratch[64u * 1024u * 1024u];

// ---------------------------------------------------------------------------
// PTX helpers
// ---------------------------------------------------------------------------
__device__ __forceinline__ uint32_t s2u(const void* p) {
    uint32_t r;
    asm("{ .reg .u64 t; cvta.to.shared.u64 t, %1; cvt.u32.u64 %0, t; }"
        : "=r"(r) : "l"(p));
    return r;
}
#define CP_ASYNC16(s, g)                                                       \
    asm volatile("cp.async.cg.shared.global [%0], [%1], 16;" ::                \
                 "r"(s), "l"(g))
#define CP_COMMIT() asm volatile("cp.async.commit_group;" ::: "memory")
#define CP_WAIT(n)  asm volatile("cp.async.wait_group %0;" :: "n"(n) : "memory")

__device__ __forceinline__ void ldm_x4(uint32_t& r0, uint32_t& r1,
                                       uint32_t& r2, uint32_t& r3,
                                       uint32_t addr) {
    asm volatile("ldmatrix.sync.aligned.m8n8.x4.shared.b16 {%0,%1,%2,%3}, [%4];"
                 : "=r"(r0), "=r"(r1), "=r"(r2), "=r"(r3) : "r"(addr));
}
// fp8 e4m3 MMA with f16 accumulators
__device__ __forceinline__ void mma16832h(uint32_t* c, const uint32_t* a,
                                          uint32_t b0, uint32_t b1) {
    asm volatile(
        "mma.sync.aligned.m16n8k32.row.col.f16.e4m3.e4m3.f16 "
        "{%0,%1}, {%2,%3,%4,%5}, {%6,%7}, {%0,%1};"
        : "+r"(c[0]), "+r"(c[1])
        : "r"(a[0]), "r"(a[1]), "r"(a[2]), "r"(a[3]), "r"(b0), "r"(b1));
}
// pack two fp32 -> e4m3x2 (lo in low byte)
__device__ __forceinline__ uint16_t pack_e4m3(float lo, float hi) {
    uint16_t r;
    asm("cvt.rn.satfinite.e4m3x2.f32 %0, %1, %2;" : "=h"(r) : "f"(hi), "f"(lo));
    return r;
}

// ---------------------------------------------------------------------------
// prep kernel: GroupNorm -> T8 (blocks 0-63), weight fp32 -> e4m3*64
// (blocks 64-1087), bias concat + rsum zero (block 1088).
// ---------------------------------------------------------------------------
__global__ __launch_bounds__(256) void prep_kernel(
    const float* __restrict__ x, const float* __restrict__ gs,
    const float* __restrict__ gb, uint8_t* __restrict__ t8,
    const float* __restrict__ wq, const float* __restrict__ wk,
    const float* __restrict__ wv, const float* __restrict__ wp,
    uint8_t* __restrict__ o01, uint8_t* __restrict__ o2,
    uint8_t* __restrict__ o3,
    const float* __restrict__ bq, const float* __restrict__ bk,
    float* __restrict__ bqk, float* __restrict__ rsum) {
    int blk = blockIdx.x;
    int tid = threadIdx.x;

    if (blk >= 1088) {           // bias concat + rsum zero
        bqk[tid]       = bq[tid];
        bqk[tid + 256] = bq[tid + 256];
        bqk[tid + 512] = bk[tid];
        bqk[tid + 768] = bk[tid + 256];
        float4* r4 = (float4*)rsum;
#pragma unroll
        for (int i = 0; i < 8; i++)
            r4[tid + i * 256] = make_float4(0.f, 0.f, 0.f, 0.f);
        return;
    }
    if (blk >= 64) {             // weight fp32 -> e4m3 * 64
        int lb = blk - 64;
        int which = lb >> 8;
        const float* in = (which == 0) ? wq : (which == 1) ? wk :
                          (which == 2) ? wv : wp;
        uint8_t* out = (which == 0) ? o01 : (which == 1) ? (o01 + 512 * 512) :
                       (which == 2) ? o2 : o3;
        int i = (lb & 255) * 256 + tid;
        float4 v = ((const float4*)in)[i];
        uint32_t w = (uint32_t)pack_e4m3(v.x * 64.f, v.y * 64.f) |
                     ((uint32_t)pack_e4m3(v.z * 64.f, v.w * 64.f) << 16);
        ((uint32_t*)out)[i] = w;
        return;
    }

    // ---- GroupNorm -> e4m3 T8[b][n][c] ----
    int b = blk >> 5;
    int g = blk & 31;
    const float* base = x + ((size_t)(b * NCH + g * 16)) * NTOK;

    float s = 0.f, ss = 0.f;
    const float4* b4 = (const float4*)base;
    for (int i = tid; i < 16 * NTOK / 4; i += 256) {
        float4 v = b4[i];
        s  += v.x + v.y + v.z + v.w;
        ss += v.x * v.x + v.y * v.y + v.z * v.z + v.w * v.w;
    }
    __shared__ float rs[256], rss[256];
    rs[tid] = s; rss[tid] = ss;
    __syncthreads();
    for (int st = 128; st > 0; st >>= 1) {
        if (tid < st) { rs[tid] += rs[tid + st]; rss[tid] += rss[tid + st]; }
        __syncthreads();
    }
    float mean = rs[0] * (1.f / 65536.f);
    float var  = rss[0] * (1.f / 65536.f) - mean * mean;
    float inv  = rsqrtf(var + 1e-6f);

    __shared__ float Acf[16], Bcf[16];
    if (tid < 16) {
        float scv = gs[g * 16 + tid], biv = gb[g * 16 + tid];
        Acf[tid] = scv * inv;
        Bcf[tid] = biv - mean * scv * inv;
    }
    __shared__ float tile[16][257];
    __syncthreads();

    for (int tb = 0; tb < 16; tb++) {
        int p0 = tb * 256;
        for (int idx = tid; idx < 4096; idx += 256) {
            int cc = idx >> 8, pp = idx & 255;
            tile[cc][pp] = base[cc * NTOK + p0 + pp] * Acf[cc] + Bcf[cc];
        }
        __syncthreads();
        // 2048 pairs of channels -> one uint16 e4m3x2 store each
        for (int idx = tid; idx < 2048; idx += 256) {
            int pp = idx >> 3, c2 = idx & 7;
            uint16_t pk = pack_e4m3(tile[c2 * 2][pp], tile[c2 * 2 + 1][pp]);
            *(uint16_t*)(t8 + ((size_t)(b * NTOK + p0 + pp)) * NCH +
                         g * 16 + c2 * 2) = pk;
        }
        __syncthreads();
    }
}

// ===========================================================================
// e4m3 mma.sync GEMM body (f16 acc): C = A[M,K].B[N,K]^T, CTA 128x128, BK=128
// (fp8), 8 warps, 3-stage cp.async, swizzled 128B rows.
// lda/ldb/sA/sB in BYTES. Epilogue modes:
//   rsum_out: C8 = exp(acc*alpha) e4m3 + row-sum atomics (ldC/sC bytes)
//   else: v = acc*(alpha or alpha/rsum_div[row]) + brow + bcol + res;
//         write Cf (fp32, ldC/sC elements) or C8 (e4m3, ldC/sC bytes)
// ===========================================================================
#define STG 32768
#define GEMM_SMEM (3 * STG)
__device__ __forceinline__ void gemm8_body(
    int bxi, int byi, int bzi,
    const uint8_t* __restrict__ A, const uint8_t* __restrict__ B,
    int K, int lda, int ldb, int ldC,
    size_t sA, size_t sB, size_t sC,
    float alpha,
    const float* __restrict__ brow, const float* __restrict__ bcol,
    const float* __restrict__ res, size_t sRes,
    float* __restrict__ Cf, uint8_t* __restrict__ C8,
    float* __restrict__ rsum_out, const float* __restrict__ rsum_div,
    int rows_total, char* smem) {
    const int tid = threadIdx.x;
    const int wid = tid >> 5, lane = tid & 31;
    const int wm = wid & 1, wn = wid >> 1;
    const int bm = byi * 128, bn = bxi * 128;
    A += (size_t)bzi * sA;
    B += (size_t)bzi * sB;
    const size_t coff = (size_t)bzi * sC;
    if (res) res += (size_t)bzi * sRes;

    const int NC = K >> 7;

    const int lr  = tid >> 2;
    const int lcb = (tid & 3) * 16;
    const uint32_t lsc = (uint32_t)((lr & 7) << 4);
    const uint32_t c0s = (uint32_t)lcb ^ lsc;
    const uint32_t c1s = c0s ^ 64u;
    const uint32_t ro0 = (uint32_t)(lr * 128);
    const uint32_t ro1 = ro0 + 64 * 128;
    const char* aR0 = (const char*)A + (size_t)(bm + lr) * lda + lcb;
    const char* aR1 = aR0 + (size_t)64 * lda;
    const char* bR0 = (const char*)B + (size_t)(bn + lr) * ldb + lcb;
    const char* bR1 = bR0 + (size_t)64 * ldb;

    uint32_t acc[4][4][2];
#pragma unroll
    for (int mi = 0; mi < 4; mi++)
#pragma unroll
        for (int ni = 0; ni < 4; ni++) {
            acc[mi][ni][0] = 0u;
            acc[mi][ni][1] = 0u;
        }

    const uint32_t msc = (uint32_t)((lane & 7) << 4);
    const uint32_t h16 = (uint32_t)((lane >> 4) << 4);
    uint32_t kc[4];
#pragma unroll
    for (int ks = 0; ks < 4; ks++) kc[ks] = ((uint32_t)(ks * 32) + h16) ^ msc;
    uint32_t arow[4], brow_off[2];
#pragma unroll
    for (int mi = 0; mi < 4; mi++)
        arow[mi] = (uint32_t)((wm * 64 + mi * 16 + (lane & 15)) * 128);
#pragma unroll
    for (int nb = 0; nb < 2; nb++)
        brow_off[nb] = (uint32_t)(16384 + (wn * 32 + nb * 16 + (lane & 15)) * 128);

    const uint32_t sbase = s2u(smem);

#define ISSUE(st_, i_)                                                         \
    do {                                                                       \
        uint32_t sa = sbase + (uint32_t)(st_) * STG;                           \
        size_t kb = (size_t)(i_) * 128;                                        \
        CP_ASYNC16(sa + ro0 + c0s,          aR0 + kb);                         \
        CP_ASYNC16(sa + ro0 + c1s,          aR0 + kb + 64);                    \
        CP_ASYNC16(sa + ro1 + c0s,          aR1 + kb);                         \
        CP_ASYNC16(sa + ro1 + c1s,          aR1 + kb + 64);                    \
        CP_ASYNC16(sa + 16384 + ro0 + c0s,  bR0 + kb);                         \
        CP_ASYNC16(sa + 16384 + ro0 + c1s,  bR0 + kb + 64);                    \
        CP_ASYNC16(sa + 16384 + ro1 + c0s,  bR1 + kb);                         \
        CP_ASYNC16(sa + 16384 + ro1 + c1s,  bR1 + kb + 64);                    \
    } while (0)
#define LOAD_FRAGS(ks_)                                                        \
    do {                                                                       \
        _Pragma("unroll")                                                      \
        for (int mi = 0; mi < 4; mi++)                                         \
            ldm_x4(areg[mi][0], areg[mi][1], areg[mi][2], areg[mi][3],         \
                   base + arow[mi] + kc[ks_]);                                 \
        _Pragma("unroll")                                                      \
        for (int nb = 0; nb < 2; nb++)                                         \
            ldm_x4(breg[nb][0], breg[nb][1], breg[nb][2], breg[nb][3],         \
                   base + brow_off[nb] + kc[ks_]);                             \
    } while (0)
#define DO_MMAS()                                                              \
    do {                                                                       \
        _Pragma("unroll")                                                      \
        for (int mi = 0; mi < 4; mi++)                                         \
            _Pragma("unroll")                                                  \
            for (int ni = 0; ni < 4; ni++) {                                   \
                uint32_t b0 = breg[ni >> 1][ni & 1];                           \
                uint32_t b1 = breg[ni >> 1][(ni & 1) + 2];                     \
                mma16832h(acc[mi][ni], areg[mi], b0, b1);                      \
            }                                                                  \
    } while (0)

    ISSUE(0, 0); CP_COMMIT();
    if (NC > 1) { ISSUE(1, 1); CP_COMMIT(); }
    else        { CP_COMMIT(); }               // keep group count consistent

    int st = 0;
    for (int i = 0; i < NC; i++) {
        if (i + 1 < NC) { CP_WAIT(1); } else { CP_WAIT(0); }
        __syncthreads();
        uint32_t base = sbase + (uint32_t)st * STG;
        uint32_t areg[4][4], breg[2][4];
        LOAD_FRAGS(0);
        if (i + 2 < NC) {
            int w2 = st + 2; if (w2 >= 3) w2 -= 3;
            ISSUE(w2, i + 2); CP_COMMIT();
        }
        DO_MMAS();
#pragma unroll
        for (int ks = 1; ks < 4; ks++) { LOAD_FRAGS(ks); DO_MMAS(); }
        st++; if (st >= 3) st = 0;
    }
#undef ISSUE
#undef LOAD_FRAGS
#undef DO_MMAS

    if (rsum_out) {
        // softmax numerator: P = exp(acc*alpha) -> e4m3, row sums via atomics
        float* rs_base = rsum_out + (size_t)bzi * rows_total;
#pragma unroll
        for (int mi = 0; mi < 4; mi++) {
#pragma unroll
            for (int h = 0; h < 2; h++) {
                int row = bm + wm * 64 + mi * 16 + (lane >> 2) + 8 * h;
                size_t rowbase = coff + (size_t)row * ldC;
                float rsum = 0.f;
#pragma unroll
                for (int ni = 0; ni < 4; ni++) {
                    int col = bn + wn * 32 + ni * 8 + (lane & 3) * 2;
                    float2 f = __half22float2(
                        *(const __half2*)&acc[mi][ni][h]);
                    float e0 = __expf(f.x * alpha);
                    float e1 = __expf(f.y * alpha);
                    rsum += e0 + e1;
                    *(uint16_t*)(C8 + rowbase + col) = pack_e4m3(e0, e1);
                }
                rsum += __shfl_xor_sync(0xFFFFFFFFu, rsum, 1);
                rsum += __shfl_xor_sync(0xFFFFFFFFu, rsum, 2);
                if ((lane & 3) == 0) atomicAdd(rs_base + row, rsum);
            }
        }
        return;
    }

    const float* rd_base =
        rsum_div ? (rsum_div + (size_t)bzi * rows_total) : nullptr;
    float bc[8];
#pragma unroll
    for (int ni = 0; ni < 4; ni++) {
        int col = bn + wn * 32 + ni * 8 + (lane & 3) * 2;
        bc[2 * ni]     = bcol ? bcol[col]     : 0.f;
        bc[2 * ni + 1] = bcol ? bcol[col + 1] : 0.f;
    }
#pragma unroll
    for (int mi = 0; mi < 4; mi++) {
#pragma unroll
        for (int h = 0; h < 2; h++) {
            int row = bm + wm * 64 + mi * 16 + (lane >> 2) + 8 * h;
            float rb = brow ? brow[row] : 0.f;
            float rscale = rd_base ? (alpha / rd_base[row]) : alpha;
            size_t rowbase = coff + (size_t)row * ldC;
#pragma unroll
            for (int ni = 0; ni < 4; ni++) {
                int col = bn + wn * 32 + ni * 8 + (lane & 3) * 2;
                float2 f = __half22float2(*(const __half2*)&acc[mi][ni][h]);
                float v0 = f.x * rscale + rb + bc[2 * ni];
                float v1 = f.y * rscale + rb + bc[2 * ni + 1];
                if (res) {
                    v0 += res[(size_t)row * ldC + col];
                    v1 += res[(size_t)row * ldC + col + 1];
                }
                if (Cf) {
                    *(float2*)(Cf + rowbase + col) = make_float2(v0, v1);
                } else {
                    *(uint16_t*)(C8 + rowbase + col) = pack_e4m3(v0, v1);
                }
            }
        }
    }
}

__global__ __launch_bounds__(256, 2) void gemm8(
    const uint8_t* __restrict__ A, const uint8_t* __restrict__ B,
    int K, int lda, int ldb, int ldC,
    size_t sA, size_t sB, size_t sC,
    float alpha,
    const float* __restrict__ brow, const float* __restrict__ bcol,
    const float* __restrict__ res, size_t sRes,
    float* __restrict__ Cf, uint8_t* __restrict__ C8,
    float* __restrict__ rsum_out, const float* __restrict__ rsum_div) {
    extern __shared__ __align__(16) char smem[];
    gemm8_body(blockIdx.x, blockIdx.y, blockIdx.z, A, B, K, lda, ldb, ldC,
               sA, sB, sC, alpha, brow, bcol, res, sRes, Cf, C8,
               rsum_out, rsum_div, gridDim.y * 128, smem);
}

// Fused QK + V launch: flat grid of 768 CTAs, all fp8.
__global__ __launch_bounds__(256, 2) void gemm_qkv8(
    const uint8_t* __restrict__ T8, const uint8_t* __restrict__ Wqk8,
    const uint8_t* __restrict__ Wv8,
    const float* __restrict__ bqk, const float* __restrict__ bv,
    uint8_t* __restrict__ QK8, uint8_t* __restrict__ V8) {
    extern __shared__ __align__(16) char smem[];
    int id = blockIdx.x;
    const float inv64 = 0.015625f;
    if (id < 512) {
        int z = id >> 8, rem = id & 255;
        gemm8_body(rem & 7, rem >> 3, z, T8, Wqk8, NCH, NCH, NCH, 1024,
                   NB1C, 0, 2 * (size_t)NB1C, inv64, nullptr, bqk,
                   nullptr, 0, nullptr, QK8, nullptr, nullptr, 0, smem);
    } else {
        int id2 = id - 512;
        int z = id2 >> 7, rem = id2 & 127;
        gemm8_body(rem & 31, rem >> 5, z, Wv8, T8, NCH, NCH, NCH, NTOK,
                   0, NB1C, NB1C, inv64, bv, nullptr,
                   nullptr, 0, nullptr, V8, nullptr, nullptr, 0, smem);
    }
}

// ---------------------------------------------------------------------------
// Orchestration: 5 launches, all GEMMs on the fp8/f16-acc path.
// ---------------------------------------------------------------------------
extern "C" void kernel_launch(void* const* d_in, const int* in_sizes, int n_in,
                              void* d_out, int out_size) {
    const float* x  = (const float*)d_in[0];
    const float* gs = (const float*)d_in[1];
    const float* gb = (const float*)d_in[2];
    const float* wq = (const float*)d_in[3];
    const float* bq = (const float*)d_in[4];
    const float* wk = (const float*)d_in[5];
    const float* bk = (const float*)d_in[6];
    const float* wv = (const float*)d_in[7];
    const float* bv = (const float*)d_in[8];
    const float* wp = (const float*)d_in[9];
    const float* bp = (const float*)d_in[10];
    float* y = (float*)d_out;

    float* scratch = nullptr;
    cudaGetSymbolAddress((void**)&scratch, g_scratch);
    char* cb = (char*)scratch;

    const size_t NB1 = (size_t)NTOK * NCH;     // 2097152
    const size_t SB1 = (size_t)NTOK * NTOK;    // 16777216

    uint8_t* T8   = (uint8_t*)cb;                             // 4 MB
    uint8_t* Wqk8 = T8 + 2 * NB1;                             // 512 KB
    uint8_t* Wv8  = Wqk8 + 512 * 1024;                        // 256 KB
    uint8_t* Wp8  = Wv8 + 512 * 512;                          // 256 KB
    float*   bqk  = (float*)(Wp8 + 512 * 512);                // 4 KB
    uint8_t* QK8  = (uint8_t*)bqk + 8192;                     // 8 MB
    uint8_t* V8   = QK8 + 4 * NB1;                            // 4 MB
    uint8_t* P8   = V8 + 2 * NB1;                             // 32 MB
    uint8_t* O8   = P8 + 2 * SB1;                             // 4 MB
    float*   rsum = (float*)(O8 + 2 * NB1);                   // 32 KB

    cudaFuncSetAttribute(gemm8, cudaFuncAttributeMaxDynamicSharedMemorySize,
                         GEMM_SMEM);
    cudaFuncSetAttribute(gemm_qkv8, cudaFuncAttributeMaxDynamicSharedMemorySize,
                         GEMM_SMEM);

    const float inv64 = 0.015625f;

    // GN -> T8, weights -> e4m3*64, bias concat, rsum zero
    prep_kernel<<<1089, 256>>>(x, gs, gb, T8, wq, wk, wv, wp,
                               Wqk8, Wv8, Wp8, bq, bk, bqk, rsum);

    // QK8 = e4m3(T8.Wqk8^T/64 + bqk)  and  V8 = e4m3(Wv8.T8^T/64 + bv)
    gemm_qkv8<<<768, 256, GEMM_SMEM>>>(T8, Wqk8, Wv8, bqk, bv, QK8, V8);

    // P8[b,n,n] = e4m3( exp((Q8.K8^T) * c^-0.5) ), rowsum accumulated
    gemm8<<<dim3(32, 32, 2), 256, GEMM_SMEM>>>(
        QK8, QK8 + 512, NCH, 1024, 1024, NTOK, 2 * NB1, 2 * NB1, SB1,
        0.044194173824159216f, nullptr, nullptr, nullptr, 0,
        nullptr, P8, rsum, nullptr);
    // O8[b,n,c] = e4m3( (P8.V8^T) / rowsum )
    gemm8<<<dim3(4, 32, 2), 256, GEMM_SMEM>>>(
        P8, V8, NTOK, NTOK, NTOK, NCH, SB1, NB1, NB1, 1.f,
        nullptr, nullptr, nullptr, 0, nullptr, O8, nullptr, rsum);
    // Y[b,c,n] = Wp8.O8^T/64 + bp + x  -> fp32
    gemm8<<<dim3(32, 4, 2), 256, GEMM_SMEM>>>(
        Wp8, O8, NCH, NCH, NCH, NTOK, 0, NB1, NB1, inv64,
        bp, nullptr, x, NB1, y, nullptr, nullptr, nullptr);
}